// round 2
// baseline (speedup 1.0000x reference)
#include <cuda_runtime.h>

#define BB 16
#define SS 4096
#define HH 768
#define TT 3
#define NSLICE 8
#define SCAN_THREADS 256
#define STEPS_PER_SLICE (SCAN_THREADS * 2)   // 512
#define NEGV (-1e30f)

// ---------------- scratch (static device globals; no allocation) ----------------
__device__ float g_em[BB * SS * TT];          // emissions, 786 KB
__device__ float g_part[BB * NSLICE * 9];     // per-slice 3x3 semiring partial products
__device__ float g_nump[BB * NSLICE];         // numerator partial sums (t >= 1)
__device__ int   g_mskp[BB * NSLICE];         // mask partial sums (t >= 1)

// stable logsumexp of 3
__device__ __forceinline__ float lse3(float a, float b, float c) {
    float m = fmaxf(a, fmaxf(b, c));
    return m + __logf(__expf(a - m) + __expf(b - m) + __expf(c - m));
}

// C = A (x) B in the (logsumexp, +) semiring, 3x3
__device__ __forceinline__ void comb3(const float* A, const float* B, float* C) {
#pragma unroll
    for (int i = 0; i < 3; i++) {
#pragma unroll
        for (int j = 0; j < 3; j++) {
            C[i * 3 + j] = lse3(A[i * 3 + 0] + B[0 * 3 + j],
                                A[i * 3 + 1] + B[1 * 3 + j],
                                A[i * 3 + 2] + B[2 * 3 + j]);
        }
    }
}

// ---------------- kernel 1: emissions = x @ W^T + b  (one warp per (b,s) row) ----
__global__ void __launch_bounds__(256) emis_kernel(const float* __restrict__ x,
                                                   const float* __restrict__ W,
                                                   const float* __restrict__ bias) {
    int gw   = (blockIdx.x * 256 + threadIdx.x) >> 5;   // row index
    int lane = threadIdx.x & 31;
    if (gw >= BB * SS) return;

    const float4* xr = reinterpret_cast<const float4*>(x) + (size_t)gw * (HH / 4);
    const float4* w4 = reinterpret_cast<const float4*>(W);

    float a0 = 0.f, a1 = 0.f, a2 = 0.f;
#pragma unroll
    for (int j = 0; j < 6; j++) {
        int idx = lane + 32 * j;                 // 0..191 (HH/4 float4s)
        float4 xv = __ldg(xr + idx);
        float4 w0 = __ldg(w4 + idx);             // W row 0
        float4 w1 = __ldg(w4 + 192 + idx);       // W row 1
        float4 w2 = __ldg(w4 + 384 + idx);       // W row 2
        a0 = fmaf(xv.x, w0.x, fmaf(xv.y, w0.y, fmaf(xv.z, w0.z, fmaf(xv.w, w0.w, a0))));
        a1 = fmaf(xv.x, w1.x, fmaf(xv.y, w1.y, fmaf(xv.z, w1.z, fmaf(xv.w, w1.w, a1))));
        a2 = fmaf(xv.x, w2.x, fmaf(xv.y, w2.y, fmaf(xv.z, w2.z, fmaf(xv.w, w2.w, a2))));
    }
#pragma unroll
    for (int off = 16; off; off >>= 1) {
        a0 += __shfl_xor_sync(0xFFFFFFFFu, a0, off);
        a1 += __shfl_xor_sync(0xFFFFFFFFu, a1, off);
        a2 += __shfl_xor_sync(0xFFFFFFFFu, a2, off);
    }
    if (lane == 0) {
        g_em[gw * 3 + 0] = a0 + __ldg(bias + 0);
        g_em[gw * 3 + 1] = a1 + __ldg(bias + 1);
        g_em[gw * 3 + 2] = a2 + __ldg(bias + 2);
    }
}

// ---------------- kernel 2: blocked CRF scan + numerator partials ----------------
// grid = BB * NSLICE blocks; block (b, slice) covers steps t in [1+512*slice, 1+512*(slice+1))
// Each thread handles 2 consecutive steps, then an order-preserving tree combine.
__global__ void __launch_bounds__(SCAN_THREADS) crf_scan_kernel(const int* __restrict__ y,
                                                                const int* __restrict__ mask,
                                                                const float* __restrict__ trans) {
    __shared__ float sP[SCAN_THREADS][9];
    __shared__ float sN[SCAN_THREADS];
    __shared__ int   sM[SCAN_THREADS];

    int tid   = threadIdx.x;
    int b     = blockIdx.x / NSLICE;
    int slice = blockIdx.x % NSLICE;
    int bS    = b * SS;

    float tr[9];
#pragma unroll
    for (int i = 0; i < 9; i++) tr[i] = __ldg(trans + i);

    int t0 = 1 + slice * STEPS_PER_SLICE + tid * 2;   // always <= SS-1
    int t1 = t0 + 1;                                  // may be == SS (guarded)

    const float* em0 = g_em + (size_t)(bS + t0) * 3;

    float P[9];
    float nsum = 0.f;
    int   msum = 0;

    // --- step t0: P = M(t0) (or identity if masked out) ---
    {
        int mk = mask[bS + t0];
        if (mk) {
            float e0 = em0[0], e1 = em0[1], e2 = em0[2];
#pragma unroll
            for (int i = 0; i < 3; i++) {
                P[i * 3 + 0] = tr[i * 3 + 0] + e0;
                P[i * 3 + 1] = tr[i * 3 + 1] + e1;
                P[i * 3 + 2] = tr[i * 3 + 2] + e2;
            }
            int yt = y[bS + t0], yp = y[bS + t0 - 1];
            nsum += tr[yp * 3 + yt] + em0[yt];
            msum += 1;
        } else {
#pragma unroll
            for (int i = 0; i < 9; i++) P[i] = NEGV;
            P[0] = 0.f; P[4] = 0.f; P[8] = 0.f;
        }
    }

    // --- step t1: P = P (x) M(t1) ---
    if (t1 < SS) {
        int mk = mask[bS + t1];
        if (mk) {
            float e0 = em0[3], e1 = em0[4], e2 = em0[5];
            float C[9];
#pragma unroll
            for (int i = 0; i < 3; i++) {
                C[i * 3 + 0] = lse3(P[i * 3 + 0] + tr[0], P[i * 3 + 1] + tr[3], P[i * 3 + 2] + tr[6]) + e0;
                C[i * 3 + 1] = lse3(P[i * 3 + 0] + tr[1], P[i * 3 + 1] + tr[4], P[i * 3 + 2] + tr[7]) + e1;
                C[i * 3 + 2] = lse3(P[i * 3 + 0] + tr[2], P[i * 3 + 1] + tr[5], P[i * 3 + 2] + tr[8]) + e2;
            }
#pragma unroll
            for (int i = 0; i < 9; i++) P[i] = C[i];

            int yt = y[bS + t1], yp = y[bS + t1 - 1];
            nsum += tr[yp * 3 + yt] + em0[3 + yt];
            msum += 1;
        }
    }

#pragma unroll
    for (int i = 0; i < 9; i++) sP[tid][i] = P[i];
    sN[tid] = nsum;
    sM[tid] = msum;
    __syncthreads();

    // order-preserving tree: at level st, thread tid (tid % 2st == 0) holds product of
    // chunks [tid, tid+2st) in sequence order: sP[tid] = sP[tid] (x) sP[tid+st]
    for (int st = 1; st < SCAN_THREADS; st <<= 1) {
        if ((tid & (2 * st - 1)) == 0) {
            float C[9];
            comb3(sP[tid], sP[tid + st], C);
#pragma unroll
            for (int i = 0; i < 9; i++) sP[tid][i] = C[i];
            sN[tid] += sN[tid + st];
            sM[tid] += sM[tid + st];
        }
        __syncthreads();
    }

    if (tid == 0) {
        int pi = b * NSLICE + slice;
#pragma unroll
        for (int i = 0; i < 9; i++) g_part[pi * 9 + i] = sP[0][i];
        g_nump[pi] = sN[0];
        g_mskp[pi] = sM[0];
    }
}

// ---------------- kernel 3: per-batch finalize + mean -----------------------------
__global__ void crf_final_kernel(const int* __restrict__ y,
                                 const int* __restrict__ mask,
                                 const float* __restrict__ start_t,
                                 const float* __restrict__ end_t,
                                 float* __restrict__ out) {
    int lane = threadIdx.x;   // 32 threads, lanes 0..15 active
    float llh = 0.f;

    if (lane < BB) {
        int b  = lane;
        int bS = b * SS;

        // chain the 8 slice partials in order
        float M[9];
#pragma unroll
        for (int i = 0; i < 9; i++) M[i] = g_part[(b * NSLICE + 0) * 9 + i];
        for (int s = 1; s < NSLICE; s++) {
            float C[9];
            comb3(M, &g_part[(b * NSLICE + s) * 9], C);
#pragma unroll
            for (int i = 0; i < 9; i++) M[i] = C[i];
        }

        // alpha0 = start + emissions[:,0]
        float a0 = start_t[0] + g_em[bS * 3 + 0];
        float a1 = start_t[1] + g_em[bS * 3 + 1];
        float a2 = start_t[2] + g_em[bS * 3 + 2];

        float af0 = lse3(a0 + M[0], a1 + M[3], a2 + M[6]);
        float af1 = lse3(a0 + M[1], a1 + M[4], a2 + M[7]);
        float af2 = lse3(a0 + M[2], a1 + M[5], a2 + M[8]);
        float denom = lse3(af0 + end_t[0], af1 + end_t[1], af2 + end_t[2]);

        // numerator
        int y0 = y[bS];
        float num = start_t[y0] + g_em[bS * 3 + y0];
        int slen = mask[bS];
        for (int s = 0; s < NSLICE; s++) {
            num  += g_nump[b * NSLICE + s];
            slen += g_mskp[b * NSLICE + s];
        }
        int ylast = y[bS + slen - 1];
        num += end_t[ylast];

        llh = num - denom;
    }

#pragma unroll
    for (int off = 16; off; off >>= 1)
        llh += __shfl_xor_sync(0xFFFFFFFFu, llh, off);

    if (lane == 0) out[0] = -llh / (float)BB;
}

// ---------------- launch ----------------------------------------------------------
extern "C" void kernel_launch(void* const* d_in, const int* in_sizes, int n_in,
                              void* d_out, int out_size) {
    const float* x     = (const float*)d_in[0];
    const int*   y     = (const int*)  d_in[1];
    const int*   mask  = (const int*)  d_in[2];
    const float* W     = (const float*)d_in[3];
    const float* bias  = (const float*)d_in[4];
    const float* st    = (const float*)d_in[5];
    const float* en    = (const float*)d_in[6];
    const float* trans = (const float*)d_in[7];
    float* out = (float*)d_out;

    // 1) emissions: one warp per (b,s) row; exactly B*S warps
    emis_kernel<<<(BB * SS) / 8, 256>>>(x, W, bias);
    // 2) blocked associative CRF scan + numerator partials
    crf_scan_kernel<<<BB * NSLICE, SCAN_THREADS>>>(y, mask, trans);
    // 3) finalize
    crf_final_kernel<<<1, 32>>>(y, mask, st, en, out);
}

// round 3
// speedup vs baseline: 1.0011x; 1.0011x over previous
#include <cuda_runtime.h>

#define BB 16
#define SS 4096
#define HH 768
#define TT 3
#define NSLICE 8
#define SCAN_THREADS 256
#define STEPS_PER_SLICE (SCAN_THREADS * 2)   // 512
#define NEGV (-1e30f)
#define ROWS_PER_WARP 8

// ---------------- scratch (static device globals; no allocation) ----------------
__device__ float g_em[BB * SS * TT];          // emissions, 786 KB
__device__ float g_part[BB * NSLICE * 9];     // per-slice 3x3 semiring partial products
__device__ float g_nump[BB * NSLICE];         // numerator partial sums (t >= 1)
__device__ int   g_mskp[BB * NSLICE];         // mask partial sums (t >= 1)

// stable logsumexp of 3
__device__ __forceinline__ float lse3(float a, float b, float c) {
    float m = fmaxf(a, fmaxf(b, c));
    return m + __logf(__expf(a - m) + __expf(b - m) + __expf(c - m));
}

// C = A (x) B in the (logsumexp, +) semiring, 3x3
__device__ __forceinline__ void comb3(const float* A, const float* B, float* C) {
#pragma unroll
    for (int i = 0; i < 3; i++) {
#pragma unroll
        for (int j = 0; j < 3; j++) {
            C[i * 3 + j] = lse3(A[i * 3 + 0] + B[0 * 3 + j],
                                A[i * 3 + 1] + B[1 * 3 + j],
                                A[i * 3 + 2] + B[2 * 3 + j]);
        }
    }
}

// ---------------- kernel 1: emissions = x @ W^T + b ------------------------------
// One warp per 8 consecutive rows. W float4s hoisted into registers per j-chunk,
// amortized over the 8 rows -> L1 wavefront traffic drops ~3x (W reloads were the
// bottleneck: 72 of 96 wf/row in the previous version).
__global__ void __launch_bounds__(256) emis_kernel(const float* __restrict__ x,
                                                   const float* __restrict__ W,
                                                   const float* __restrict__ bias) {
    int gw   = (blockIdx.x * 256 + threadIdx.x) >> 5;   // warp index
    int lane = threadIdx.x & 31;
    int row0 = gw * ROWS_PER_WARP;
    if (row0 >= BB * SS) return;

    const float4* x4 = reinterpret_cast<const float4*>(x);
    const float4* w4 = reinterpret_cast<const float4*>(W);

    float a0[ROWS_PER_WARP], a1[ROWS_PER_WARP], a2[ROWS_PER_WARP];
#pragma unroll
    for (int r = 0; r < ROWS_PER_WARP; r++) { a0[r] = 0.f; a1[r] = 0.f; a2[r] = 0.f; }

#pragma unroll
    for (int j = 0; j < 6; j++) {
        int idx = lane + 32 * j;                  // 0..191 (HH/4 float4s)
        float4 w0 = __ldg(w4 + idx);              // W row 0 (L1-resident, 1 load / 8 rows)
        float4 w1 = __ldg(w4 + 192 + idx);        // W row 1
        float4 w2 = __ldg(w4 + 384 + idx);        // W row 2
#pragma unroll
        for (int r = 0; r < ROWS_PER_WARP; r++) {
            float4 xv = __ldg(x4 + (size_t)(row0 + r) * (HH / 4) + idx);
            a0[r] = fmaf(xv.x, w0.x, fmaf(xv.y, w0.y, fmaf(xv.z, w0.z, fmaf(xv.w, w0.w, a0[r]))));
            a1[r] = fmaf(xv.x, w1.x, fmaf(xv.y, w1.y, fmaf(xv.z, w1.z, fmaf(xv.w, w1.w, a1[r]))));
            a2[r] = fmaf(xv.x, w2.x, fmaf(xv.y, w2.y, fmaf(xv.z, w2.z, fmaf(xv.w, w2.w, a2[r]))));
        }
    }

    // butterfly reduce: every lane ends with the full row sums
#pragma unroll
    for (int off = 16; off; off >>= 1) {
#pragma unroll
        for (int r = 0; r < ROWS_PER_WARP; r++) {
            a0[r] += __shfl_xor_sync(0xFFFFFFFFu, a0[r], off);
            a1[r] += __shfl_xor_sync(0xFFFFFFFFu, a1[r], off);
            a2[r] += __shfl_xor_sync(0xFFFFFFFFu, a2[r], off);
        }
    }

    // lanes 0..7 each write one row (3 floats)
    if (lane < ROWS_PER_WARP) {
        float b0 = __ldg(bias + 0), b1 = __ldg(bias + 1), b2 = __ldg(bias + 2);
        int row = row0 + lane;
        g_em[row * 3 + 0] = a0[lane] + b0;
        g_em[row * 3 + 1] = a1[lane] + b1;
        g_em[row * 3 + 2] = a2[lane] + b2;
    }
}

// ---------------- kernel 2: blocked CRF scan + numerator partials ----------------
// grid = BB * NSLICE blocks; block (b, slice) covers steps t in [1+512*slice, 1+512*(slice+1))
// Each thread handles 2 consecutive steps, then an order-preserving tree combine.
__global__ void __launch_bounds__(SCAN_THREADS) crf_scan_kernel(const int* __restrict__ y,
                                                                const int* __restrict__ mask,
                                                                const float* __restrict__ trans) {
    __shared__ float sP[SCAN_THREADS][9];
    __shared__ float sN[SCAN_THREADS];
    __shared__ int   sM[SCAN_THREADS];

    int tid   = threadIdx.x;
    int b     = blockIdx.x / NSLICE;
    int slice = blockIdx.x % NSLICE;
    int bS    = b * SS;

    float tr[9];
#pragma unroll
    for (int i = 0; i < 9; i++) tr[i] = __ldg(trans + i);

    int t0 = 1 + slice * STEPS_PER_SLICE + tid * 2;   // always <= SS-1
    int t1 = t0 + 1;                                  // may be == SS (guarded)

    const float* em0 = g_em + (size_t)(bS + t0) * 3;

    float P[9];
    float nsum = 0.f;
    int   msum = 0;

    // --- step t0: P = M(t0) (or identity if masked out) ---
    {
        int mk = mask[bS + t0];
        if (mk) {
            float e0 = em0[0], e1 = em0[1], e2 = em0[2];
#pragma unroll
            for (int i = 0; i < 3; i++) {
                P[i * 3 + 0] = tr[i * 3 + 0] + e0;
                P[i * 3 + 1] = tr[i * 3 + 1] + e1;
                P[i * 3 + 2] = tr[i * 3 + 2] + e2;
            }
            int yt = y[bS + t0], yp = y[bS + t0 - 1];
            nsum += tr[yp * 3 + yt] + em0[yt];
            msum += 1;
        } else {
#pragma unroll
            for (int i = 0; i < 9; i++) P[i] = NEGV;
            P[0] = 0.f; P[4] = 0.f; P[8] = 0.f;
        }
    }

    // --- step t1: P = P (x) M(t1) ---
    if (t1 < SS) {
        int mk = mask[bS + t1];
        if (mk) {
            float e0 = em0[3], e1 = em0[4], e2 = em0[5];
            float C[9];
#pragma unroll
            for (int i = 0; i < 3; i++) {
                C[i * 3 + 0] = lse3(P[i * 3 + 0] + tr[0], P[i * 3 + 1] + tr[3], P[i * 3 + 2] + tr[6]) + e0;
                C[i * 3 + 1] = lse3(P[i * 3 + 0] + tr[1], P[i * 3 + 1] + tr[4], P[i * 3 + 2] + tr[7]) + e1;
                C[i * 3 + 2] = lse3(P[i * 3 + 0] + tr[2], P[i * 3 + 1] + tr[5], P[i * 3 + 2] + tr[8]) + e2;
            }
#pragma unroll
            for (int i = 0; i < 9; i++) P[i] = C[i];

            int yt = y[bS + t1], yp = y[bS + t1 - 1];
            nsum += tr[yp * 3 + yt] + em0[3 + yt];
            msum += 1;
        }
    }

#pragma unroll
    for (int i = 0; i < 9; i++) sP[tid][i] = P[i];
    sN[tid] = nsum;
    sM[tid] = msum;
    __syncthreads();

    // order-preserving tree: sP[tid] = sP[tid] (x) sP[tid+st]
    for (int st = 1; st < SCAN_THREADS; st <<= 1) {
        if ((tid & (2 * st - 1)) == 0) {
            float C[9];
            comb3(sP[tid], sP[tid + st], C);
#pragma unroll
            for (int i = 0; i < 9; i++) sP[tid][i] = C[i];
            sN[tid] += sN[tid + st];
            sM[tid] += sM[tid + st];
        }
        __syncthreads();
    }

    if (tid == 0) {
        int pi = b * NSLICE + slice;
#pragma unroll
        for (int i = 0; i < 9; i++) g_part[pi * 9 + i] = sP[0][i];
        g_nump[pi] = sN[0];
        g_mskp[pi] = sM[0];
    }
}

// ---------------- kernel 3: per-batch finalize + mean -----------------------------
__global__ void crf_final_kernel(const int* __restrict__ y,
                                 const int* __restrict__ mask,
                                 const float* __restrict__ start_t,
                                 const float* __restrict__ end_t,
                                 float* __restrict__ out) {
    int lane = threadIdx.x;   // 32 threads, lanes 0..15 active
    float llh = 0.f;

    if (lane < BB) {
        int b  = lane;
        int bS = b * SS;

        // chain the 8 slice partials in order
        float M[9];
#pragma unroll
        for (int i = 0; i < 9; i++) M[i] = g_part[(b * NSLICE + 0) * 9 + i];
        for (int s = 1; s < NSLICE; s++) {
            float C[9];
            comb3(M, &g_part[(b * NSLICE + s) * 9], C);
#pragma unroll
            for (int i = 0; i < 9; i++) M[i] = C[i];
        }

        // alpha0 = start + emissions[:,0]
        float a0 = start_t[0] + g_em[bS * 3 + 0];
        float a1 = start_t[1] + g_em[bS * 3 + 1];
        float a2 = start_t[2] + g_em[bS * 3 + 2];

        float af0 = lse3(a0 + M[0], a1 + M[3], a2 + M[6]);
        float af1 = lse3(a0 + M[1], a1 + M[4], a2 + M[7]);
        float af2 = lse3(a0 + M[2], a1 + M[5], a2 + M[8]);
        float denom = lse3(af0 + end_t[0], af1 + end_t[1], af2 + end_t[2]);

        // numerator
        int y0 = y[bS];
        float num = start_t[y0] + g_em[bS * 3 + y0];
        int slen = mask[bS];
        for (int s = 0; s < NSLICE; s++) {
            num  += g_nump[b * NSLICE + s];
            slen += g_mskp[b * NSLICE + s];
        }
        int ylast = y[bS + slen - 1];
        num += end_t[ylast];

        llh = num - denom;
    }

#pragma unroll
    for (int off = 16; off; off >>= 1)
        llh += __shfl_xor_sync(0xFFFFFFFFu, llh, off);

    if (lane == 0) out[0] = -llh / (float)BB;
}

// ---------------- launch ----------------------------------------------------------
extern "C" void kernel_launch(void* const* d_in, const int* in_sizes, int n_in,
                              void* d_out, int out_size) {
    const float* x     = (const float*)d_in[0];
    const int*   y     = (const int*)  d_in[1];
    const int*   mask  = (const int*)  d_in[2];
    const float* W     = (const float*)d_in[3];
    const float* bias  = (const float*)d_in[4];
    const float* st    = (const float*)d_in[5];
    const float* en    = (const float*)d_in[6];
    const float* trans = (const float*)d_in[7];
    float* out = (float*)d_out;

    // 1) emissions: one warp per 8 rows -> B*S/8 warps
    emis_kernel<<<(BB * SS) / (8 * ROWS_PER_WARP), 256>>>(x, W, bias);
    // 2) blocked associative CRF scan + numerator partials
    crf_scan_kernel<<<BB * NSLICE, SCAN_THREADS>>>(y, mask, trans);
    // 3) finalize
    crf_final_kernel<<<1, 32>>>(y, mask, st, en, out);
}